// round 4
// baseline (speedup 1.0000x reference)
#include <cuda_runtime.h>
#include <cuda_bf16.h>

// Contamination: out = 0.8*x + 0.2 * avg(valid neighbors at {-8,0,8}^2 \ {0,0})
// x: [B=8, C=32, H=512, W=512] fp32, k=8.
//
// R4: L1tex was the binding pipe (80.5%). Column neighbors are exactly +/-2
// lanes within the warp (blockDim.x=32 spans 32 consecutive float4 columns),
// so fetch them via __shfl instead of LDG: 1 full load + tiny edge loads per
// row instead of 3 full loads. Row-roll carries sums AND the center value, so
// no ctr reload. ~2.3x fewer L1 ops; shuffle pipe (idle) absorbs the rest.

namespace {

constexpr int H  = 512;
constexpr int W  = 512;
constexpr int K  = 8;
constexpr int W4 = W / 4;       // 128 float4 per row

__device__ __forceinline__ float4 f4zero() { return make_float4(0.f, 0.f, 0.f, 0.f); }

__device__ __forceinline__ float4 f4add(float4 a, float4 b) {
    return make_float4(a.x + b.x, a.y + b.y, a.z + b.z, a.w + b.w);
}

__device__ __forceinline__ float4 shfl_up4(float4 v) {
    float4 r;
    r.x = __shfl_up_sync(0xffffffffu, v.x, 2);
    r.y = __shfl_up_sync(0xffffffffu, v.y, 2);
    r.z = __shfl_up_sync(0xffffffffu, v.z, 2);
    r.w = __shfl_up_sync(0xffffffffu, v.w, 2);
    return r;
}

__device__ __forceinline__ float4 shfl_dn4(float4 v) {
    float4 r;
    r.x = __shfl_down_sync(0xffffffffu, v.x, 2);
    r.y = __shfl_down_sync(0xffffffffu, v.y, 2);
    r.z = __shfl_down_sync(0xffffffffu, v.z, 2);
    r.w = __shfl_down_sync(0xffffffffu, v.w, 2);
    return r;
}

// Load row r (warp-uniform r), return horizontal 3-col sum and the center.
// Left/right neighbors come from +/-2-lane shuffles; only lanes 0-1 / 30-31
// issue small predicated loads for the out-of-warp columns.
__device__ __forceinline__ float4 row_sum(const float4* __restrict__ pin,
                                          int r, int c4, int lane,
                                          bool hasL, bool hasR,
                                          float4& center) {
    if (r < 0 || r >= H) {             // warp-uniform branch
        center = f4zero();
        return f4zero();
    }
    const float4* __restrict__ row = pin + (long)r * W4;
    float4 c = row[c4];

    float4 el = f4zero(), er = f4zero();
    if (lane < 2 && hasL)   el = row[c4 - 2];   // only at warp/image left edge
    if (lane >= 30 && hasR) er = row[c4 + 2];   // only at warp/image right edge

    float4 l = shfl_up4(c);
    float4 rr = shfl_dn4(c);
    if (lane < 2)   l = el;
    if (lane >= 30) rr = er;

    center = c;
    return f4add(f4add(c, l), rr);
}

__global__ __launch_bounds__(256, 6)
void contam_kernel(const float4* __restrict__ in, float4* __restrict__ out) {
    const int lane = threadIdx.x;                    // warp spans 32 float4 cols
    const int c4   = blockIdx.x * 32 + lane;         // 0..127
    const int row0 = blockIdx.y * 32 + threadIdx.y;  // first output row
    const long plane = blockIdx.z;

    const float4* __restrict__ pin  = in  + plane * (long)(H * W4);
    float4* __restrict__       pout = out + plane * (long)(H * W4);

    const bool hasL = (c4 >= 2);
    const bool hasR = (c4 <= W4 - 3);
    const int  nc   = 1 + (int)hasL + (int)hasR;

    float4 dummy, Ccur;
    float4 Sprev = row_sum(pin, row0 - K, c4, lane, hasL, hasR, dummy);
    float4 Scur  = row_sum(pin, row0,     c4, lane, hasL, hasR, Ccur);

    #pragma unroll
    for (int ry = 0; ry < 4; ry++) {
        const int h = row0 + ry * K;

        float4 Cnext;
        float4 Snext = row_sum(pin, h + K, c4, lane, hasL, hasR, Cnext);

        const int nr = 1 + (int)(h >= K) + (int)(h < H - K);
        const float scale = __fdividef(0.2f, (float)(nr * nc - 1));

        float4 acc = f4add(f4add(Sprev, Scur), Snext);

        float4 o;
        o.x = 0.8f * Ccur.x + scale * (acc.x - Ccur.x);
        o.y = 0.8f * Ccur.y + scale * (acc.y - Ccur.y);
        o.z = 0.8f * Ccur.z + scale * (acc.z - Ccur.z);
        o.w = 0.8f * Ccur.w + scale * (acc.w - Ccur.w);

        __stcs(&pout[(long)h * W4 + c4], o);

        Sprev = Scur;
        Scur  = Snext;
        Ccur  = Cnext;
    }
}

} // namespace

extern "C" void kernel_launch(void* const* d_in, const int* in_sizes, int n_in,
                              void* d_out, int out_size) {
    const float4* x = (const float4*)d_in[0];
    float4* out = (float4*)d_out;

    const int planes = in_sizes[0] / (H * W);   // 256

    dim3 block(32, 8, 1);
    dim3 grid(W4 / 32, H / 32, planes);         // (4, 16, 256)
    contam_kernel<<<grid, block>>>(x, out);
}

// round 5
// speedup vs baseline: 1.1030x; 1.1030x over previous
#include <cuda_runtime.h>
#include <cuda_bf16.h>

// Contamination: out = 0.8*x + 0.2 * avg(valid neighbors at {-8,0,8}^2 \ {0,0})
// x: [B=8, C=32, H=512, W=512] fp32, k=8.
//
// R5 = R3 (best: 101us, 32 regs) with the block-residency cap lifted:
//   __launch_bounds__(256, 8) -> 64 warps/SM possible (R3's lb(256,7) pinned
//   occupancy at 56/64 = 87%). Same rolling horizontal-sum structure, same
//   batched 4-load iterations, same streaming stores.
// Micro: fp32 divide replaced by constant select (count in {3,5,8}).

namespace {

constexpr int H  = 512;
constexpr int W  = 512;
constexpr int K  = 8;
constexpr int W4 = W / 4;       // 128 float4 per row

__device__ __forceinline__ float4 f4add(float4 a, float4 b) {
    return make_float4(a.x + b.x, a.y + b.y, a.z + b.z, a.w + b.w);
}

// horizontal 3-column sum for row r (zeros if r out of range)
__device__ __forceinline__ float4 hsum_row(const float4* __restrict__ pin,
                                           int r, int c4, bool hasL, bool hasR) {
    float4 s = make_float4(0.f, 0.f, 0.f, 0.f);
    if (r >= 0 && r < H) {
        const float4* __restrict__ row = pin + (long)r * W4;
        s = row[c4];
        if (hasL) s = f4add(s, row[c4 - 2]);
        if (hasR) s = f4add(s, row[c4 + 2]);
    }
    return s;
}

__global__ __launch_bounds__(256, 8)
void contam_kernel(const float4* __restrict__ in, float4* __restrict__ out) {
    const int c4   = blockIdx.x * 32 + threadIdx.x;   // float4 column, 0..127
    const int row0 = blockIdx.y * 32 + threadIdx.y;   // first output row
    const long plane = blockIdx.z;

    const float4* __restrict__ pin  = in  + plane * (long)(H * W4);
    float4* __restrict__       pout = out + plane * (long)(H * W4);

    const bool hasL = (c4 >= 2);
    const bool hasR = (c4 <= W4 - 3);
    const int  nc   = 1 + (int)hasL + (int)hasR;

    float4 Sprev = hsum_row(pin, row0 - K, c4, hasL, hasR);
    float4 Scur  = hsum_row(pin, row0,     c4, hasL, hasR);

    #pragma unroll
    for (int ry = 0; ry < 4; ry++) {
        const int h  = row0 + ry * K;
        const int rn = h + K;
        const bool vn = (rn < H);

        // ---- batched loads: 3 next-row cols + ctr, all independent ----
        const float4* __restrict__ rowN = pin + (long)(vn ? rn : h) * W4;
        float4 n1 = rowN[c4];                                     // next center col
        float4 n0 = hasL ? rowN[c4 - 2] : make_float4(0,0,0,0);   // next left
        float4 n2 = hasR ? rowN[c4 + 2] : make_float4(0,0,0,0);   // next right
        float4 ctr = pin[(long)h * W4 + c4];                      // L1 hit (reload)

        float4 Snext = vn ? f4add(f4add(n1, n0), n2)
                          : make_float4(0.f, 0.f, 0.f, 0.f);

        const int nr = 1 + (int)(h >= K) + (int)vn;
        // count = nr*nc - 1 in {3,5,8}  <=>  nr+nc in {4,5,6}
        const int s  = nr + nc;
        const float scale = (s == 6) ? 0.025f            // 0.2/8
                          : (s == 5) ? 0.04f             // 0.2/5
                                     : 0.066666667f;     // 0.2/3

        float4 acc = f4add(f4add(Sprev, Scur), Snext);

        float4 o;
        o.x = 0.8f * ctr.x + scale * (acc.x - ctr.x);
        o.y = 0.8f * ctr.y + scale * (acc.y - ctr.y);
        o.z = 0.8f * ctr.z + scale * (acc.z - ctr.z);
        o.w = 0.8f * ctr.w + scale * (acc.w - ctr.w);

        __stcs(&pout[(long)h * W4 + c4], o);

        Sprev = Scur;
        Scur  = Snext;
    }
}

} // namespace

extern "C" void kernel_launch(void* const* d_in, const int* in_sizes, int n_in,
                              void* d_out, int out_size) {
    const float4* x = (const float4*)d_in[0];
    float4* out = (float4*)d_out;

    const int planes = in_sizes[0] / (H * W);   // 256

    dim3 block(32, 8, 1);
    dim3 grid(W4 / 32, H / 32, planes);         // (4, 16, 256)
    contam_kernel<<<grid, block>>>(x, out);
}